// round 14
// baseline (speedup 1.0000x reference)
#include <cuda_runtime.h>
#include <cuda_fp16.h>
#include <cstdint>
#include <math.h>

// ---------------- scratch (static device globals; no allocation) ----------------
__device__ float g_q[16 * 4096];
__device__ float g_s[16 * 4096];
__device__ float g_y[16 * 256];
__device__ float g_ctx[16 * 256];
// x as fp16, SAME layout as x: [b][c][n]
__device__ __half g_xh[(size_t)16 * 256 * 4096];
// W_v rows (257..512) fp16, row-major [256 m][256 k]
__device__ __half g_wh[256 * 256];

__device__ __forceinline__ uint32_t smem_u32(const void* p) {
    uint32_t a;
    asm("{ .reg .u64 t; cvta.to.shared.u64 t, %1; cvt.u32.u64 %0, t; }" : "=r"(a) : "l"(p));
    return a;
}

#define LDSM_X4(r, addr) \
    asm volatile("ldmatrix.sync.aligned.m8n8.x4.shared.b16 {%0,%1,%2,%3}, [%4];" \
        : "=r"((r)[0]), "=r"((r)[1]), "=r"((r)[2]), "=r"((r)[3]) : "r"(addr))
#define LDSM_X4T(r, addr) \
    asm volatile("ldmatrix.sync.aligned.m8n8.x4.trans.shared.b16 {%0,%1,%2,%3}, [%4];" \
        : "=r"((r)[0]), "=r"((r)[1]), "=r"((r)[2]), "=r"((r)[3]) : "r"(addr))
// f16-out MMA, c = zero: d = a*b. Independent d-regs -> back-to-back issue.
#define MMA_F16Z(d0, d1, a, b0, b1, z) \
    asm volatile("mma.sync.aligned.m16n8k16.row.col.f16.f16.f16.f16 " \
        "{%0,%1}, {%2,%3,%4,%5}, {%6,%7}, {%8,%8};" \
        : "=r"(d0), "=r"(d1) \
        : "r"((a)[0]), "r"((a)[1]), "r"((a)[2]), "r"((a)[3]), "r"(b0), "r"(b1), "r"(z))
#define CP_ASYNC16(dst, src) \
    asm volatile("cp.async.cg.shared.global [%0], [%1], 16;" :: "r"(dst), "l"(src))
#define CP_COMMIT() asm volatile("cp.async.commit_group;" ::: "memory")
#define CP_WAIT(n)  asm volatile("cp.async.wait_group %0;" :: "n"(n) : "memory")

// ---------------------------------------------------------------------------
// Kernel A: W_v (rows 257..512) -> fp16.
// ---------------------------------------------------------------------------
__global__ __launch_bounds__(256) void conv_w(const float* __restrict__ W)
{
    int r = blockIdx.x, c = threadIdx.x;
    g_wh[r * 256 + c] = __float2half_rn(W[(size_t)(257 + r) * 256 + c]);
}

// ---------------------------------------------------------------------------
// Kernel B: x -> fp16 (same layout) and q[b,n] = sum_c W[0,c]*x[b,c,n].
// ---------------------------------------------------------------------------
__global__ __launch_bounds__(256) void conv_xq(const float* __restrict__ x,
                                               const float* __restrict__ W)
{
    __shared__ float s_wq[256];
    __shared__ float s_red[4][256];
    const int b = blockIdx.y;
    const int nBase = blockIdx.x * 256;
    const int t = threadIdx.x;
    const int cq = t >> 6;
    const int n = (t & 63) * 4;

    s_wq[t] = W[t];  // W row 0 = q weights
    __syncthreads();

    float qp0 = 0.f, qp1 = 0.f, qp2 = 0.f, qp3 = 0.f;
#pragma unroll 8
    for (int c = cq; c < 256; c += 4) {
        size_t idx = ((size_t)b * 256 + c) * 4096 + nBase + n;
        float4 v = *(const float4*)(x + idx);
        __half2 h01 = __floats2half2_rn(v.x, v.y);
        __half2 h23 = __floats2half2_rn(v.z, v.w);
        uint2 pk;
        pk.x = *(uint32_t*)&h01;
        pk.y = *(uint32_t*)&h23;
        *(uint2*)(g_xh + idx) = pk;
        float wq = s_wq[c];
        qp0 += wq * v.x; qp1 += wq * v.y; qp2 += wq * v.z; qp3 += wq * v.w;
    }
    *(float4*)&s_red[cq][n] = make_float4(qp0, qp1, qp2, qp3);
    __syncthreads();
    g_q[b * 4096 + nBase + t] =
        s_red[0][t] + s_red[1][t] + s_red[2][t] + s_red[3][t];
}

// ---------------------------------------------------------------------------
// Kernel C: softmax over q (16 x 4096), fp32 scores out.
// ---------------------------------------------------------------------------
__global__ __launch_bounds__(512) void softmax_k()
{
    const int b = blockIdx.x;
    const float4* q4 = (const float4*)(g_q + b * 4096);
    float4* s4 = (float4*)(g_s + b * 4096);

    float4 v0 = q4[threadIdx.x];
    float4 v1 = q4[threadIdx.x + 512];

    float m = fmaxf(fmaxf(fmaxf(v0.x, v0.y), fmaxf(v0.z, v0.w)),
                    fmaxf(fmaxf(v1.x, v1.y), fmaxf(v1.z, v1.w)));
    __shared__ float redm[16];
    __shared__ float reds[16];
#pragma unroll
    for (int o = 16; o > 0; o >>= 1) m = fmaxf(m, __shfl_xor_sync(0xffffffffu, m, o));
    if ((threadIdx.x & 31) == 0) redm[threadIdx.x >> 5] = m;
    __syncthreads();
    float gm = redm[0];
#pragma unroll
    for (int i = 1; i < 16; i++) gm = fmaxf(gm, redm[i]);

    v0.x = __expf(v0.x - gm); v0.y = __expf(v0.y - gm);
    v0.z = __expf(v0.z - gm); v0.w = __expf(v0.w - gm);
    v1.x = __expf(v1.x - gm); v1.y = __expf(v1.y - gm);
    v1.z = __expf(v1.z - gm); v1.w = __expf(v1.w - gm);

    float sum = v0.x + v0.y + v0.z + v0.w + v1.x + v1.y + v1.z + v1.w;
#pragma unroll
    for (int o = 16; o > 0; o >>= 1) sum += __shfl_xor_sync(0xffffffffu, sum, o);
    if ((threadIdx.x & 31) == 0) reds[threadIdx.x >> 5] = sum;
    __syncthreads();
    float tot = 0.f;
#pragma unroll
    for (int i = 0; i < 16; i++) tot += reds[i];
    float inv = 1.f / tot;

    v0.x *= inv; v0.y *= inv; v0.z *= inv; v0.w *= inv;
    v1.x *= inv; v1.y *= inv; v1.z *= inv; v1.w *= inv;
    s4[threadIdx.x] = v0;
    s4[threadIdx.x + 512] = v1;
}

// ---------------------------------------------------------------------------
// Kernel D: y[b,c] = sum_n x[b,c,n] * s[b,n]  (fp16 x, fp32 s/accumulate).
// ---------------------------------------------------------------------------
__global__ __launch_bounds__(256) void y_kernel()
{
    const int c = blockIdx.x, b = blockIdx.y;
    const uint4* xr = (const uint4*)(g_xh + ((size_t)b * 256 + c) * 4096);
    const float4* sr = (const float4*)(g_s + b * 4096);
    float acc = 0.f;
#pragma unroll
    for (int it = 0; it < 2; it++) {
        int i = it * 256 + threadIdx.x;
        uint4 xv = xr[i];
        float4 s0 = sr[i * 2];
        float4 s1 = sr[i * 2 + 1];
        float2 a = __half22float2(*(__half2*)&xv.x);
        float2 bq = __half22float2(*(__half2*)&xv.y);
        float2 cc = __half22float2(*(__half2*)&xv.z);
        float2 d = __half22float2(*(__half2*)&xv.w);
        acc += a.x * s0.x + a.y * s0.y + bq.x * s0.z + bq.y * s0.w;
        acc += cc.x * s1.x + cc.y * s1.y + d.x * s1.z + d.y * s1.w;
    }
#pragma unroll
    for (int o = 16; o > 0; o >>= 1) acc += __shfl_xor_sync(0xffffffffu, acc, o);
    __shared__ float red[8];
    if ((threadIdx.x & 31) == 0) red[threadIdx.x >> 5] = acc;
    __syncthreads();
    if (threadIdx.x == 0) {
        float tsum = 0.f;
#pragma unroll
        for (int i = 0; i < 8; i++) tsum += red[i];
        g_y[b * 256 + c] = tsum;
    }
}

// ---------------------------------------------------------------------------
// Kernel E: ctx[b,d] = sum_c W[1+d,c] * y[b,c]. One warp per d, coalesced.
// ---------------------------------------------------------------------------
__global__ __launch_bounds__(256) void ctx_kernel(const float* __restrict__ W)
{
    const int b = blockIdx.x;
    const int w = threadIdx.x >> 5, l = threadIdx.x & 31;
    const int d = blockIdx.y * 8 + w;
    __shared__ float ys[256];
    ys[threadIdx.x] = g_y[b * 256 + threadIdx.x];
    __syncthreads();
    const float* wr = W + (size_t)(1 + d) * 256;
    float acc = 0.f;
#pragma unroll
    for (int c = l; c < 256; c += 32) acc += wr[c] * ys[c];
#pragma unroll
    for (int o = 16; o > 0; o >>= 1) acc += __shfl_xor_sync(0xffffffffu, acc, o);
    if (l == 0) g_ctx[b * 256 + d] = acc;
}

// ---------------------------------------------------------------------------
// Kernel F: GEMM rate experiment — f16-output MMA, BATCH-ISSUED:
// per ks-group, all 16 MMAs write independent d-reg pairs (no consumer in
// between -> tensor pipe issues back-to-back), then one promote pass adds
// them into fp32 accumulators (idle fma pipe). Per-k16 promotion precision
// already proven passing (R12: 3.76e-4).
// CTA tile 128(m) x 128(n), 256 thr, 2-stage cp.async ring, race-free waits.
// Epilogue: out = relu(V) * ctx.
// ---------------------------------------------------------------------------
#define STAGE_BYTES 32768

__global__ __launch_bounds__(256) void gemm_tc(float* __restrict__ out)
{
    extern __shared__ char sm[];
    __shared__ float s_ctx[128];

    const int nBase = blockIdx.x * 128;
    const int mBase = blockIdx.y * 128;
    const int b = blockIdx.z;
    const uint32_t smb = smem_u32(sm);

    const int t = threadIdx.x;
    const int w = t >> 5, L = t & 31;
    const int mw = w & 1, nw = w >> 1;

    if (t < 128) s_ctx[t] = g_ctx[b * 256 + mBase + t];

    const int ra = t >> 1, ca = t & 1;
    const int rb = t >> 2, cb = t & 3;

    auto stage = [&](int ch, int buf) {
        const int k0 = ch * 64;
        const uint32_t base = smb + buf * STAGE_BYTES;
#pragma unroll
        for (int i = 0; i < 4; i++) {
            int c16 = ca * 4 + i;
            uint32_t offA = (uint32_t)(ra * 128 + c16 * 16);
            uint32_t swA = offA ^ ((offA >> 3) & 0x70);
            CP_ASYNC16(base + swA, g_wh + (size_t)(mBase + ra) * 256 + k0 + c16 * 8);
            int c16b = cb * 4 + i;
            uint32_t offB = (uint32_t)(rb * 256 + c16b * 16);
            uint32_t swB = offB ^ (((offB >> 8) & 0xF) << 4);
            CP_ASYNC16(base + 16384 + swB,
                       g_xh + ((size_t)b * 256 + k0 + rb) * 4096 + nBase + c16b * 8);
        }
        CP_COMMIT();
    };

    float acc[4][4][4];
#pragma unroll
    for (int i = 0; i < 4; i++)
#pragma unroll
        for (int j = 0; j < 4; j++)
#pragma unroll
            for (int k = 0; k < 4; k++) acc[i][j][k] = 0.f;

    const int rowL = L & 15;
    const int selL = L >> 4;
    const uint32_t zreg = 0u;

    stage(0, 0);
    stage(1, 1);

#pragma unroll
    for (int ch = 0; ch < 4; ch++) {
        if (ch < 3) { CP_WAIT(1); } else { CP_WAIT(0); }   // race-free waits
        __syncthreads();
        const uint32_t base = smb + (ch & 1) * STAGE_BYTES;
#pragma unroll
        for (int ks = 0; ks < 4; ks++) {
            uint32_t Ah[4][4], B[2][4];
#pragma unroll
            for (int mf = 0; mf < 4; mf++) {
                uint32_t offA = (uint32_t)((mw * 64 + mf * 16 + rowL) * 128 +
                                           (ks * 2 + selL) * 16);
                LDSM_X4(Ah[mf], base + (offA ^ ((offA >> 3) & 0x70)));
            }
#pragma unroll
            for (int ng = 0; ng < 2; ng++) {
                uint32_t offB = (uint32_t)((ks * 16 + rowL) * 256 +
                                           (nw * 4 + ng * 2 + selL) * 16);
                LDSM_X4T(B[ng], base + 16384 + (offB ^ (((offB >> 8) & 0xF) << 4)));
            }
            // --- batch 1: issue ALL 16 MMAs into independent d-regs ---
            uint32_t dt[4][4][2];
#pragma unroll
            for (int mf = 0; mf < 4; mf++)
#pragma unroll
                for (int nf = 0; nf < 4; nf++) {
                    const int ng = nf >> 1, p = (nf & 1) * 2;
                    MMA_F16Z(dt[mf][nf][0], dt[mf][nf][1],
                             Ah[mf], B[ng][p], B[ng][p + 1], zreg);
                }
            // --- batch 2: promote all to fp32 accumulators ---
#pragma unroll
            for (int mf = 0; mf < 4; mf++)
#pragma unroll
                for (int nf = 0; nf < 4; nf++) {
                    float2 lo = __half22float2(*(__half2*)&dt[mf][nf][0]);
                    float2 hi = __half22float2(*(__half2*)&dt[mf][nf][1]);
                    acc[mf][nf][0] += lo.x;
                    acc[mf][nf][1] += lo.y;
                    acc[mf][nf][2] += hi.x;
                    acc[mf][nf][3] += hi.y;
                }
        }
        if (ch < 2) {
            __syncthreads();
            stage(ch + 2, ch & 1);
        }
    }

    // ---- epilogue: out = relu(V) * ctx ----
    const int gid = L >> 2, tig = L & 3;
#pragma unroll
    for (int mf = 0; mf < 4; mf++) {
        const int r0 = mw * 64 + mf * 16 + gid;
        const float c0 = s_ctx[r0], c1 = s_ctx[r0 + 8];
        float* o0 = out + ((size_t)b * 256 + mBase + r0) * 4096 + nBase;
        float* o1 = o0 + (size_t)8 * 4096;
#pragma unroll
        for (int nf = 0; nf < 4; nf++) {
            const int col = nw * 32 + nf * 8 + tig * 2;
            float2 v0 = make_float2(fmaxf(acc[mf][nf][0], 0.f) * c0,
                                    fmaxf(acc[mf][nf][1], 0.f) * c0);
            float2 v1 = make_float2(fmaxf(acc[mf][nf][2], 0.f) * c1,
                                    fmaxf(acc[mf][nf][3], 0.f) * c1);
            *(float2*)(o0 + col) = v0;
            *(float2*)(o1 + col) = v1;
        }
    }
}

// ---------------------------------------------------------------------------
extern "C" void kernel_launch(void* const* d_in, const int* in_sizes, int n_in,
                              void* d_out, int out_size)
{
    const float* x = (const float*)d_in[0];  // (16, 256, 64, 64) f32
    const float* W = (const float*)d_in[1];  // (513, 256) f32
    float* out = (float*)d_out;              // (16, 256, 64, 64) f32

    cudaFuncSetAttribute(gemm_tc, cudaFuncAttributeMaxDynamicSharedMemorySize,
                         2 * STAGE_BYTES);

    conv_w<<<256, 256>>>(W);
    conv_xq<<<dim3(16, 16), 256>>>(x, W);
    softmax_k<<<16, 512>>>();
    y_kernel<<<dim3(256, 16), 256>>>();
    ctx_kernel<<<dim3(16, 32), 256>>>(W);
    gemm_tc<<<dim3(32, 2, 16), 256, 2 * STAGE_BYTES>>>(out);
}

// round 15
// speedup vs baseline: 1.2911x; 1.2911x over previous
#include <cuda_runtime.h>
#include <cuda_fp16.h>
#include <cstdint>
#include <math.h>

// ---------------- scratch (static device globals; no allocation) ----------------
__device__ float g_q[16 * 4096];
__device__ float g_s[16 * 4096];
__device__ float g_y[16 * 256];
__device__ float g_ctx[16 * 256];
// x as fp16, SAME layout as x: [b][c][n]
__device__ __half g_xh[(size_t)16 * 256 * 4096];
// W_v rows (257..512) fp16, row-major [256 m][256 k]
__device__ __half g_wh[256 * 256];

__device__ __forceinline__ uint32_t smem_u32(const void* p) {
    uint32_t a;
    asm("{ .reg .u64 t; cvta.to.shared.u64 t, %1; cvt.u32.u64 %0, t; }" : "=r"(a) : "l"(p));
    return a;
}

#define LDSM_X4(r, addr) \
    asm volatile("ldmatrix.sync.aligned.m8n8.x4.shared.b16 {%0,%1,%2,%3}, [%4];" \
        : "=r"((r)[0]), "=r"((r)[1]), "=r"((r)[2]), "=r"((r)[3]) : "r"(addr))
#define LDSM_X4T(r, addr) \
    asm volatile("ldmatrix.sync.aligned.m8n8.x4.trans.shared.b16 {%0,%1,%2,%3}, [%4];" \
        : "=r"((r)[0]), "=r"((r)[1]), "=r"((r)[2]), "=r"((r)[3]) : "r"(addr))
#define MMA_F16(d, a, b0, b1) \
    asm volatile("mma.sync.aligned.m16n8k16.row.col.f32.f16.f16.f32 " \
        "{%0,%1,%2,%3}, {%4,%5,%6,%7}, {%8,%9}, {%0,%1,%2,%3};" \
        : "+f"((d)[0]), "+f"((d)[1]), "+f"((d)[2]), "+f"((d)[3]) \
        : "r"((a)[0]), "r"((a)[1]), "r"((a)[2]), "r"((a)[3]), "r"(b0), "r"(b1))
#define CP_ASYNC16(dst, src) \
    asm volatile("cp.async.cg.shared.global [%0], [%1], 16;" :: "r"(dst), "l"(src))
#define CP_COMMIT() asm volatile("cp.async.commit_group;" ::: "memory")
#define CP_WAIT(n)  asm volatile("cp.async.wait_group %0;" :: "n"(n) : "memory")

// ---------------------------------------------------------------------------
// Kernel B: x -> fp16 (same layout), q[b,n] = sum_c W[0,c]*x[b,c,n], AND
// (fused, one row per block) W_v rows 257..512 -> fp16.
// Grid (16 n-tiles of 256, 16 b), 256 threads.
// ---------------------------------------------------------------------------
__global__ __launch_bounds__(256) void conv_xq(const float* __restrict__ x,
                                               const float* __restrict__ W)
{
    __shared__ float s_wq[256];
    __shared__ float s_red[4][256];
    const int b = blockIdx.y;
    const int nBase = blockIdx.x * 256;
    const int t = threadIdx.x;
    const int cq = t >> 6;          // 0..3 (c phase)
    const int n = (t & 63) * 4;     // n offset within tile

    // fused conv_w: block (bx,by) converts W_v row (by*16+bx)
    {
        const int r = blockIdx.y * 16 + blockIdx.x;
        g_wh[r * 256 + t] = __float2half_rn(W[(size_t)(257 + r) * 256 + t]);
    }

    s_wq[t] = W[t];  // W row 0 = q weights
    __syncthreads();

    float qp0 = 0.f, qp1 = 0.f, qp2 = 0.f, qp3 = 0.f;
#pragma unroll 8
    for (int c = cq; c < 256; c += 4) {
        size_t idx = ((size_t)b * 256 + c) * 4096 + nBase + n;
        float4 v = *(const float4*)(x + idx);
        __half2 h01 = __floats2half2_rn(v.x, v.y);
        __half2 h23 = __floats2half2_rn(v.z, v.w);
        uint2 pk;
        pk.x = *(uint32_t*)&h01;
        pk.y = *(uint32_t*)&h23;
        *(uint2*)(g_xh + idx) = pk;
        float wq = s_wq[c];
        qp0 += wq * v.x; qp1 += wq * v.y; qp2 += wq * v.z; qp3 += wq * v.w;
    }
    *(float4*)&s_red[cq][n] = make_float4(qp0, qp1, qp2, qp3);
    __syncthreads();
    g_q[b * 4096 + nBase + t] =
        s_red[0][t] + s_red[1][t] + s_red[2][t] + s_red[3][t];
}

// ---------------------------------------------------------------------------
// Kernel C: softmax over q (16 x 4096), fp32 scores out.
// ---------------------------------------------------------------------------
__global__ __launch_bounds__(512) void softmax_k()
{
    const int b = blockIdx.x;
    const float4* q4 = (const float4*)(g_q + b * 4096);
    float4* s4 = (float4*)(g_s + b * 4096);

    float4 v0 = q4[threadIdx.x];
    float4 v1 = q4[threadIdx.x + 512];

    float m = fmaxf(fmaxf(fmaxf(v0.x, v0.y), fmaxf(v0.z, v0.w)),
                    fmaxf(fmaxf(v1.x, v1.y), fmaxf(v1.z, v1.w)));
    __shared__ float redm[16];
    __shared__ float reds[16];
#pragma unroll
    for (int o = 16; o > 0; o >>= 1) m = fmaxf(m, __shfl_xor_sync(0xffffffffu, m, o));
    if ((threadIdx.x & 31) == 0) redm[threadIdx.x >> 5] = m;
    __syncthreads();
    float gm = redm[0];
#pragma unroll
    for (int i = 1; i < 16; i++) gm = fmaxf(gm, redm[i]);

    v0.x = __expf(v0.x - gm); v0.y = __expf(v0.y - gm);
    v0.z = __expf(v0.z - gm); v0.w = __expf(v0.w - gm);
    v1.x = __expf(v1.x - gm); v1.y = __expf(v1.y - gm);
    v1.z = __expf(v1.z - gm); v1.w = __expf(v1.w - gm);

    float sum = v0.x + v0.y + v0.z + v0.w + v1.x + v1.y + v1.z + v1.w;
#pragma unroll
    for (int o = 16; o > 0; o >>= 1) sum += __shfl_xor_sync(0xffffffffu, sum, o);
    if ((threadIdx.x & 31) == 0) reds[threadIdx.x >> 5] = sum;
    __syncthreads();
    float tot = 0.f;
#pragma unroll
    for (int i = 0; i < 16; i++) tot += reds[i];
    float inv = 1.f / tot;

    v0.x *= inv; v0.y *= inv; v0.z *= inv; v0.w *= inv;
    v1.x *= inv; v1.y *= inv; v1.z *= inv; v1.w *= inv;
    s4[threadIdx.x] = v0;
    s4[threadIdx.x + 512] = v1;
}

// ---------------------------------------------------------------------------
// Kernel D: y[b,c] = sum_n x[b,c,n] * s[b,n]  (fp16 x, fp32 s/accumulate).
// TWO c-rows per warp (s loaded ONCE per pair -> halves s L2 traffic).
// Grid (16, 16), 256 thr = 8 warps x 2 rows = 16 rows/block.
// ---------------------------------------------------------------------------
__global__ __launch_bounds__(256) void y_kernel()
{
    const int b = blockIdx.y;
    const int t = threadIdx.x;
    const int w = t >> 5, L = t & 31;
    const int c0 = blockIdx.x * 16 + w * 2;    // this warp's row pair

    const uint4* xr0 = (const uint4*)(g_xh + ((size_t)b * 256 + c0) * 4096);
    const uint4* xr1 = (const uint4*)(g_xh + ((size_t)b * 256 + c0 + 1) * 4096);
    const float4* sr = (const float4*)(g_s + b * 4096);

    float acc0 = 0.f, acc1 = 0.f;
#pragma unroll
    for (int g = 0; g < 4; g++) {
        uint4 xv0[4], xv1[4];
        float4 sv[8];
#pragma unroll
        for (int j = 0; j < 4; j++) {
            int i = (g * 4 + j) * 32 + L;       // uint4 index (8 halves)
            xv0[j] = xr0[i];
            xv1[j] = xr1[i];
            sv[j * 2]     = sr[i * 2];
            sv[j * 2 + 1] = sr[i * 2 + 1];
        }
#pragma unroll
        for (int j = 0; j < 4; j++) {
            float4 s0 = sv[j * 2], s1 = sv[j * 2 + 1];
            float2 a0 = __half22float2(*(__half2*)&xv0[j].x);
            float2 a1 = __half22float2(*(__half2*)&xv0[j].y);
            float2 a2 = __half22float2(*(__half2*)&xv0[j].z);
            float2 a3 = __half22float2(*(__half2*)&xv0[j].w);
            acc0 += a0.x * s0.x + a0.y * s0.y + a1.x * s0.z + a1.y * s0.w;
            acc0 += a2.x * s1.x + a2.y * s1.y + a3.x * s1.z + a3.y * s1.w;
            float2 b0 = __half22float2(*(__half2*)&xv1[j].x);
            float2 b1 = __half22float2(*(__half2*)&xv1[j].y);
            float2 b2 = __half22float2(*(__half2*)&xv1[j].z);
            float2 b3 = __half22float2(*(__half2*)&xv1[j].w);
            acc1 += b0.x * s0.x + b0.y * s0.y + b1.x * s0.z + b1.y * s0.w;
            acc1 += b2.x * s1.x + b2.y * s1.y + b3.x * s1.z + b3.y * s1.w;
        }
    }
#pragma unroll
    for (int o = 16; o > 0; o >>= 1) {
        acc0 += __shfl_xor_sync(0xffffffffu, acc0, o);
        acc1 += __shfl_xor_sync(0xffffffffu, acc1, o);
    }
    if (L == 0) {
        g_y[b * 256 + c0]     = acc0;
        g_y[b * 256 + c0 + 1] = acc1;
    }
}

// ---------------------------------------------------------------------------
// Kernel E: ctx[b,d] = sum_c W[1+d,c] * y[b,c]. One warp per d, coalesced.
// ---------------------------------------------------------------------------
__global__ __launch_bounds__(256) void ctx_kernel(const float* __restrict__ W)
{
    const int b = blockIdx.x;
    const int w = threadIdx.x >> 5, l = threadIdx.x & 31;
    const int d = blockIdx.y * 8 + w;
    __shared__ float ys[256];
    ys[threadIdx.x] = g_y[b * 256 + threadIdx.x];
    __syncthreads();
    const float* wr = W + (size_t)(1 + d) * 256;
    float acc = 0.f;
#pragma unroll
    for (int c = l; c < 256; c += 32) acc += wr[c] * ys[c];
#pragma unroll
    for (int o = 16; o > 0; o >>= 1) acc += __shfl_xor_sync(0xffffffffu, acc, o);
    if (l == 0) g_ctx[b * 256 + d] = acc;
}

// ---------------------------------------------------------------------------
// Kernel F: mma.sync fp16 GEMM (fp32 accumulators), V = Wv @ x.
// Measured-best (R6/R13): CTA tile 256(m) x 128(n), x read once.
// 512 threads, 16 warps, warp tile 64x32. 4 K-chunks fully prefetched
// (4 stages x 48KB). Race-free waits 3/2/1/0. Epilogue: relu(V)*ctx.
// ---------------------------------------------------------------------------
#define STAGE_BYTES 49152

__global__ __launch_bounds__(512, 1) void gemm_tc(float* __restrict__ out)
{
    extern __shared__ char sm[];
    __shared__ float s_ctx[256];

    const int nBase = blockIdx.x * 128;
    const int b = blockIdx.y;
    const uint32_t smb = smem_u32(sm);

    const int t = threadIdx.x;
    const int w = t >> 5, L = t & 31;
    const int mw = w & 3, nw = w >> 2;   // 4 m-warps x 4 n-warps

    if (t < 256) s_ctx[t] = g_ctx[b * 256 + t];

    // ---- prefetch all 4 K-chunks ----
#pragma unroll
    for (int ch = 0; ch < 4; ch++) {
        const int k0 = ch * 64;
        const uint32_t base = smb + ch * STAGE_BYTES;
#pragma unroll
        for (int i = 0; i < 4; i++) {          // A: 2048 16B-chunks / 512 thr
            int u = i * 512 + t;
            int ra = u >> 3, ca = u & 7;
            uint32_t offA = (uint32_t)(ra * 128 + ca * 16);
            uint32_t swA = offA ^ ((offA >> 3) & 0x70);
            CP_ASYNC16(base + swA, g_wh + (size_t)ra * 256 + k0 + ca * 8);
        }
#pragma unroll
        for (int i = 0; i < 2; i++) {          // B: 1024 16B-chunks / 512 thr
            int u = i * 512 + t;
            int rb = u >> 4, cb = u & 15;
            uint32_t offB = (uint32_t)(rb * 256 + cb * 16);
            uint32_t swB = offB ^ (((offB >> 8) & 0xF) << 4);
            CP_ASYNC16(base + 32768 + swB,
                       g_xh + ((size_t)b * 256 + k0 + rb) * 4096 + nBase + cb * 8);
        }
        CP_COMMIT();
    }

    float acc[4][4][4];
#pragma unroll
    for (int i = 0; i < 4; i++)
#pragma unroll
        for (int j = 0; j < 4; j++)
#pragma unroll
            for (int k = 0; k < 4; k++) acc[i][j][k] = 0.f;

    const int rowL = L & 15;
    const int selL = L >> 4;

#define DO_CHUNK(CH, WAITN)                                                     \
    {                                                                           \
        CP_WAIT(WAITN);                                                         \
        __syncthreads();                                                        \
        const uint32_t base = smb + (CH) * STAGE_BYTES;                         \
        _Pragma("unroll")                                                       \
        for (int ks = 0; ks < 4; ks++) {                                        \
            uint32_t Ah[4][4], B[2][4];                                         \
            _Pragma("unroll")                                                   \
            for (int mf = 0; mf < 4; mf++) {                                    \
                uint32_t offA = (uint32_t)((mw * 64 + mf * 16 + rowL) * 128 +   \
                                           (ks * 2 + selL) * 16);               \
                LDSM_X4(Ah[mf], base + (offA ^ ((offA >> 3) & 0x70)));          \
            }                                                                   \
            _Pragma("unroll")                                                   \
            for (int ng = 0; ng < 2; ng++) {                                    \
                uint32_t offB = (uint32_t)((ks * 16 + rowL) * 256 +             \
                                           (nw * 4 + ng * 2 + selL) * 16);      \
                LDSM_X4T(B[ng], base + 32768 +                                  \
                                (offB ^ (((offB >> 8) & 0xF) << 4)));           \
            }                                                                   \
            _Pragma("unroll")                                                   \
            for (int mf = 0; mf < 4; mf++)                                      \
                _Pragma("unroll")                                               \
                for (int nf = 0; nf < 4; nf++) {                                \
                    const int ng = nf >> 1, p = (nf & 1) * 2;                   \
                    MMA_F16(acc[mf][nf], Ah[mf], B[ng][p], B[ng][p + 1]);       \
                }                                                               \
        }                                                                       \
    }

    DO_CHUNK(0, 3)
    DO_CHUNK(1, 2)
    DO_CHUNK(2, 1)
    DO_CHUNK(3, 0)
#undef DO_CHUNK

    // ---- epilogue: out = relu(V) * ctx ----
    const int gid = L >> 2, tig = L & 3;
#pragma unroll
    for (int mf = 0; mf < 4; mf++) {
        const int r0 = mw * 64 + mf * 16 + gid;
        const float c0 = s_ctx[r0], c1 = s_ctx[r0 + 8];
        float* o0 = out + ((size_t)b * 256 + r0) * 4096 + nBase;
        float* o1 = o0 + (size_t)8 * 4096;
#pragma unroll
        for (int nf = 0; nf < 4; nf++) {
            const int col = nw * 32 + nf * 8 + tig * 2;
            float2 v0 = make_float2(fmaxf(acc[mf][nf][0], 0.f) * c0,
                                    fmaxf(acc[mf][nf][1], 0.f) * c0);
            float2 v1 = make_float2(fmaxf(acc[mf][nf][2], 0.f) * c1,
                                    fmaxf(acc[mf][nf][3], 0.f) * c1);
            *(float2*)(o0 + col) = v0;
            *(float2*)(o1 + col) = v1;
        }
    }
}

// ---------------------------------------------------------------------------
extern "C" void kernel_launch(void* const* d_in, const int* in_sizes, int n_in,
                              void* d_out, int out_size)
{
    const float* x = (const float*)d_in[0];  // (16, 256, 64, 64) f32
    const float* W = (const float*)d_in[1];  // (513, 256) f32
    float* out = (float*)d_out;              // (16, 256, 64, 64) f32

    cudaFuncSetAttribute(gemm_tc, cudaFuncAttributeMaxDynamicSharedMemorySize,
                         4 * STAGE_BYTES);

    conv_xq<<<dim3(16, 16), 256>>>(x, W);    // also converts W_v (fused)
    softmax_k<<<16, 512>>>();
    y_kernel<<<dim3(16, 16), 256>>>();
    ctx_kernel<<<dim3(16, 32), 256>>>(W);
    gemm_tc<<<dim3(32, 16), 512, 4 * STAGE_BYTES>>>(out);
}